// round 11
// baseline (speedup 1.0000x reference)
#include <cuda_runtime.h>
#include <cuda_bf16.h>
#include <math.h>

#define BB 32
#define TT 256
#define EE 256
#define HHD 256
#define KK 12
#define TSTART 10
#define TSTOP 11
#define NEGV (-10000.0f)

// ------------------- static device scratch -------------------
__device__ float g_X[2][TT * BB][EE];           // gathered embeddings (fwd, bwd-reversed)
__device__ float g_G[2][TT][256][BB][4];        // gate pre-activations [dir][t][u][b][gate]
__device__ float g_h[2][2][BB][HHD];            // h double buffer [parity][dir][b][u]
__device__ float g_Hcat[BB][TT][512];           // concatenated hidden states
__device__ float g_feats[BB][TT][KK];           // emission features
__device__ unsigned g_flags[128];               // per-block step flags

// ------------------- init: zero flags, seed h0 -------------------
__global__ void k_init(const float* __restrict__ h0) {
    int i = blockIdx.x * blockDim.x + threadIdx.x;
    if (i < 128) g_flags[i] = 0u;
    if (i < 2 * BB * HHD) ((float*)g_h[0])[i] = h0[i];   // parity 0 = input for t=0
}

// ------------------- embedding gather (fwd + reversed bwd) -------------------
__global__ void k_gather(const int* __restrict__ sent, const int* __restrict__ lens,
                         const float* __restrict__ emb) {
    int row = blockIdx.x;              // row = t*32 + b
    int t = row >> 5, b = row & 31;
    int e = threadIdx.x;               // 256
    int len = lens[b];
    int pos = (t < len) ? (len - 1 - t) : t;
    int tf = sent[b * TT + t];
    int tb = sent[b * TT + pos];
    g_X[0][row][e] = emb[tf * EE + e];
    g_X[1][row][e] = emb[tb * EE + e];
}

// ------------------- input-projection GEMM (fp32) -------------------
// C[row=(t,b)][j] = X[row,:] . Wih[j,:] + bih[j] + bhh[j], written permuted to g_G
#define GP 68
__global__ void k_gemm(const float* __restrict__ Wf, const float* __restrict__ Wb,
                       const float* __restrict__ bihf, const float* __restrict__ bhhf,
                       const float* __restrict__ bihb, const float* __restrict__ bhhb) {
    __shared__ __align__(16) float Xs[16][GP];
    __shared__ __align__(16) float Ws[16][GP];
    int dir  = blockIdx.z;
    int row0 = blockIdx.y * 64;
    int j0   = blockIdx.x * 64;
    const float* W = dir ? Wb : Wf;
    const float* X = &g_X[dir][0][0];
    int tid = threadIdx.x;             // 256
    int tx = tid & 15, ty = tid >> 4;
    int lk = tid & 15, lr = tid >> 4;

    float acc[4][4];
#pragma unroll
    for (int i = 0; i < 4; i++)
#pragma unroll
        for (int j = 0; j < 4; j++) acc[i][j] = 0.f;

    for (int k0 = 0; k0 < 256; k0 += 16) {
        __syncthreads();
#pragma unroll
        for (int it = 0; it < 4; it++) {
            int r = lr + it * 16;
            Xs[lk][r] = X[(row0 + r) * EE + k0 + lk];
            Ws[lk][r] = W[(j0 + r) * EE + k0 + lk];
        }
        __syncthreads();
#pragma unroll
        for (int kk = 0; kk < 16; kk++) {
            float4 xa = *(const float4*)&Xs[kk][ty * 4];
            float4 wb = *(const float4*)&Ws[kk][tx * 4];
            float xr[4] = {xa.x, xa.y, xa.z, xa.w};
            float wr[4] = {wb.x, wb.y, wb.z, wb.w};
#pragma unroll
            for (int i = 0; i < 4; i++)
#pragma unroll
                for (int j = 0; j < 4; j++) acc[i][j] += xr[i] * wr[j];
        }
    }
    // epilogue: add biases, scatter to [dir][t][u][b][gate]
#pragma unroll
    for (int i = 0; i < 4; i++) {
        int row = row0 + ty * 4 + i;
        int t = row >> 5, b = row & 31;
#pragma unroll
        for (int j = 0; j < 4; j++) {
            int jg = j0 + tx * 4 + j;
            int gate = jg >> 8, u = jg & 255;
            float bsum = dir ? (bihb[jg] + bhhb[jg]) : (bihf[jg] + bhhf[jg]);
            g_G[dir][t][u][b][gate] = acc[i][j] + bsum;
        }
    }
}

// ------------------- persistent recurrent LSTM -------------------
__device__ __forceinline__ float fsig(float x) { return 1.f / (1.f + __expf(-x)); }

__global__ void __launch_bounds__(128, 1)
k_lstm(const float* __restrict__ Whhf, const float* __restrict__ Whhb,
       const float* __restrict__ c0, const int* __restrict__ lens) {
    // static shared: exactly 48KB
    __shared__ __align__(16) float w_sh[256 * 32];   // [v][u_l][gate] 32KB
    __shared__ __align__(16) float h_sh[16 * 256];   // [b_l][v] XOR-swizzled chunks, 16KB

    int bid  = blockIdx.x;
    int dir  = bid >> 6;
    int grp  = (bid >> 5) & 1;
    int uslc = bid & 31;
    int tid  = threadIdx.x;            // 128
    int u_l  = tid & 7, b_l = tid >> 3;
    int u = uslc * 8 + u_l;
    int b = grp * 16 + b_l;
    const float* Whh = dir ? Whhb : Whhf;

    // load Whh slice (32 rows): w_sh[v*32 + ul*4 + g] = Whh[(g*256 + uslc*8 + ul)][v]
    for (int i = tid; i < 32 * 256; i += 128) {
        int v = i & 255;
        int ug = i >> 8;                 // ul*4 + g
        int ul2 = ug >> 2, g2 = ug & 3;
        w_sh[v * 32 + ul2 * 4 + g2] = Whh[(g2 * 256 + uslc * 8 + ul2) * HHD + v];
    }
    float c = c0[(dir * BB + b) * HHD + u];
    int len = lens[b];
    unsigned* flagbase = g_flags + (bid & ~31);   // this (dir,grp) group's 32 flags
    int xsw = b_l & 3;
    const float4* w4 = (const float4*)w_sh;
    __syncthreads();

    for (int t = 0; t < TT; t++) {
        // prefetch gate pre-activations (independent of h)
        float4 gp = *(const float4*)&g_G[dir][t][u][b][0];

        // wait for all peer blocks to have produced step-t input
        if (tid < 32) {
            unsigned v;
            const unsigned* fp = flagbase + tid;
            do {
                asm volatile("ld.acquire.gpu.u32 %0, [%1];" : "=r"(v) : "l"(fp) : "memory");
            } while (v < (unsigned)t);
        }
        __syncthreads();

        // restage h (16 batches x 256) from L2-coherent buffer, XOR-swizzled
        {
            const float4* src = (const float4*)&g_h[t & 1][dir][grp * 16][0];
            for (int i = tid; i < 1024; i += 128) {
                float4 hv = __ldcg(src + i);
                int bb2 = i >> 6, cc = i & 63;
                *(float4*)&h_sh[bb2 * 256 + ((cc ^ (bb2 & 3)) << 2)] = hv;
            }
        }
        __syncthreads();

        // GEMV: 4 gates x 256
        float ai = 0.f, af = 0.f, ag = 0.f, ao = 0.f;
        const float* hrow = h_sh + b_l * 256;
        for (int v = 0; v < 256; v += 4) {
            float4 h4 = *(const float4*)&hrow[((v >> 2) ^ xsw) << 2];
            float4 w0 = w4[(v + 0) * 8 + u_l];
            float4 w1 = w4[(v + 1) * 8 + u_l];
            float4 w2 = w4[(v + 2) * 8 + u_l];
            float4 w3 = w4[(v + 3) * 8 + u_l];
            ai += w0.x * h4.x; af += w0.y * h4.x; ag += w0.z * h4.x; ao += w0.w * h4.x;
            ai += w1.x * h4.y; af += w1.y * h4.y; ag += w1.z * h4.y; ao += w1.w * h4.y;
            ai += w2.x * h4.z; af += w2.y * h4.z; ag += w2.z * h4.z; ao += w2.w * h4.z;
            ai += w3.x * h4.w; af += w3.y * h4.w; ag += w3.z * h4.w; ao += w3.w * h4.w;
        }
        ai += gp.x; af += gp.y; ag += gp.z; ao += gp.w;
        float ig = fsig(ai), fg = fsig(af), gg = tanhf(ag), og = fsig(ao);
        c = fg * c + ig * gg;
        float h = og * tanhf(c);

        __stcg(&g_h[(t + 1) & 1][dir][b][u], h);
        int pos = dir ? ((t < len) ? (len - 1 - t) : t) : t;
        g_Hcat[b][pos][dir * 256 + u] = h;

        __threadfence();
        __syncthreads();
        if (tid == 0) {
            unsigned nv = (unsigned)(t + 1);
            asm volatile("st.release.gpu.u32 [%0], %1;" :: "l"(&g_flags[bid]), "r"(nv) : "memory");
        }
    }
}

// ------------------- emission features: Hcat @ W_out^T + b_out -------------------
__global__ void k_feats(const float* __restrict__ Wout, const float* __restrict__ bout) {
    __shared__ float Wsh[12 * 516];
    __shared__ float Hsh[8 * 516];
    int blk = blockIdx.x;              // 1024 blocks, 8 rows each
    int tid = threadIdx.x;             // 128
    for (int i = tid; i < 12 * 512; i += 128) Wsh[(i >> 9) * 516 + (i & 511)] = Wout[i];
    int row0 = blk * 8;                // row = b*256 + t
    for (int i = tid; i < 8 * 512; i += 128)
        Hsh[(i >> 9) * 516 + (i & 511)] = ((const float*)g_Hcat)[(row0 + (i >> 9)) * 512 + (i & 511)];
    __syncthreads();
    if (tid < 96) {
        int rl = tid / 12, k = tid % 12;
        float s = bout[k];
        const float* wr = &Wsh[k * 516];
        const float* hr = &Hsh[rl * 516];
        for (int hh = 0; hh < 512; hh++) s += wr[hh] * hr[hh];
        ((float*)g_feats)[(row0 + rl) * 12 + k] = s;
    }
}

// ------------------- Viterbi DP + backtrace -------------------
__global__ void k_viterbi(const float* __restrict__ trans, const int* __restrict__ lens,
                          float* __restrict__ out) {
    __shared__ float tr[144];
    __shared__ float fv[8][13];
    __shared__ unsigned char bp[TT][8][12];
    __shared__ int lsh[8];
    int b0 = blockIdx.x * 8;
    int tid = threadIdx.x;             // 128
    // FIX: strided load — 128 threads must fill all 144 entries
    for (int i = tid; i < 144; i += 128) tr[i] = trans[i];
    if (tid < 8) lsh[tid] = lens[b0 + tid];
    int rl = tid / 12, k = tid % 12;
    bool act = tid < 96;
    if (act) fv[rl][k] = (k == TSTART) ? 0.f : NEGV;
    __syncthreads();

    float trk[12];
    if (act) {
#pragma unroll
        for (int p = 0; p < 12; p++) trk[p] = tr[k * 12 + p];
    }
    int len = act ? lsh[rl] : 0;
    int bg = b0 + rl;

    for (int t = 0; t < TT; t++) {
        float nf = 0.f;
        if (act) {
            float feat = ((const float*)g_feats)[(bg * TT + t) * 12 + k];
            float best = fv[rl][0] + trk[0];
            int bpi = 0;
#pragma unroll
            for (int p = 1; p < 12; p++) {
                float s = fv[rl][p] + trk[p];
                if (s > best) { best = s; bpi = p; }   // strict > => first max (jnp.argmax)
            }
            bp[t][rl][k] = (unsigned char)bpi;
            nf = (t < len) ? (best + feat) : fv[rl][k];
        }
        __syncthreads();
        if (act) fv[rl][k] = nf;
        __syncthreads();
    }

    if (tid < 8) {
        int r = tid;
        int bgl = b0 + r;
        int ln = lsh[r];
        float best = fv[r][0] + tr[TSTOP * 12 + 0];
        int tag = 0;
        for (int p = 1; p < 12; p++) {
            float s = fv[r][p] + tr[TSTOP * 12 + p];
            if (s > best) { best = s; tag = p; }
        }
        out[bgl] = best;                               // path score
        for (int t = TT - 1; t >= 0; t--) {
            bool m = t < ln;
            out[BB + bgl * TT + t] = m ? (float)tag : -1.0f;
            if (m) tag = bp[t][r][tag];
        }
    }
}

// ------------------- launch -------------------
extern "C" void kernel_launch(void* const* d_in, const int* in_sizes, int n_in,
                              void* d_out, int out_size) {
    const int*   sent  = (const int*)d_in[0];
    const int*   lens  = (const int*)d_in[1];
    const float* emb   = (const float*)d_in[2];
    const float* Wihf  = (const float*)d_in[3];
    const float* Whhf  = (const float*)d_in[4];
    const float* bihf  = (const float*)d_in[5];
    const float* bhhf  = (const float*)d_in[6];
    const float* Wihb  = (const float*)d_in[7];
    const float* Whhb  = (const float*)d_in[8];
    const float* bihb  = (const float*)d_in[9];
    const float* bhhb  = (const float*)d_in[10];
    const float* h0    = (const float*)d_in[11];
    const float* c0    = (const float*)d_in[12];
    const float* Wout  = (const float*)d_in[13];
    const float* bout  = (const float*)d_in[14];
    const float* trans = (const float*)d_in[15];
    float* out = (float*)d_out;

    k_init<<<64, 256>>>(h0);
    k_gather<<<TT * BB, 256>>>(sent, lens, emb);
    dim3 gg(16, 128, 2);
    k_gemm<<<gg, 256>>>(Wihf, Wihb, bihf, bhhf, bihb, bhhb);
    k_lstm<<<128, 128>>>(Whhf, Whhb, c0, lens);
    k_feats<<<1024, 128>>>(Wout, bout);
    k_viterbi<<<4, 128>>>(trans, lens, out);
}

// round 13
// speedup vs baseline: 1.8435x; 1.8435x over previous
#include <cuda_runtime.h>
#include <cuda_bf16.h>
#include <math.h>

#define BB 32
#define TT 256
#define EE 256
#define HHD 256
#define KK 12
#define TSTART 10
#define TSTOP 11
#define NEGV (-10000.0f)

// ------------------- static device scratch -------------------
__device__ float g_X[2][TT * BB][EE];           // gathered embeddings (fwd, bwd-reversed)
__device__ float g_G2[2][TT][BB][1024];         // gate pre-activations [dir][t][b][jg], jg=g*256+u
__device__ float g_h[2][2][BB][HHD];            // h double buffer [parity][dir][b][u]
__device__ float g_Hcat[BB][TT][512];           // concatenated hidden states
__device__ float g_feats[BB][TT][KK];           // emission features
__device__ unsigned g_ctr[4][TT];               // per-(group,step) arrival counters

// ------------------- init: zero counters, seed h0 -------------------
__global__ void k_init(const float* __restrict__ h0) {
    int i = blockIdx.x * blockDim.x + threadIdx.x;
    if (i < 4 * TT) ((unsigned*)g_ctr)[i] = 0u;
    if (i < 2 * BB * HHD) ((float*)g_h[0])[i] = h0[i];   // parity 0 = input for t=0
}

// ------------------- embedding gather (fwd + reversed bwd) -------------------
__global__ void k_gather(const int* __restrict__ sent, const int* __restrict__ lens,
                         const float* __restrict__ emb) {
    int row = blockIdx.x;              // row = t*32 + b
    int t = row >> 5, b = row & 31;
    int e = threadIdx.x;               // 256
    int len = lens[b];
    int pos = (t < len) ? (len - 1 - t) : t;
    int tf = sent[b * TT + t];
    int tb = sent[b * TT + pos];
    g_X[0][row][e] = emb[tf * EE + e];
    g_X[1][row][e] = emb[tb * EE + e];
}

// ------------------- input-projection GEMM (fp32) -------------------
// g_G2[dir][t][b][jg] = X[(t,b),:] . Wih[jg,:] + bih[jg] + bhh[jg]
#define GP 68
__global__ void k_gemm(const float* __restrict__ Wf, const float* __restrict__ Wb,
                       const float* __restrict__ bihf, const float* __restrict__ bhhf,
                       const float* __restrict__ bihb, const float* __restrict__ bhhb) {
    __shared__ __align__(16) float Xs[16][GP];
    __shared__ __align__(16) float Ws[16][GP];
    int dir  = blockIdx.z;
    int row0 = blockIdx.y * 64;
    int j0   = blockIdx.x * 64;
    const float* W = dir ? Wb : Wf;
    const float* X = &g_X[dir][0][0];
    int tid = threadIdx.x;             // 256
    int tx = tid & 15, ty = tid >> 4;
    int lk = tid & 15, lr = tid >> 4;

    float acc[4][4];
#pragma unroll
    for (int i = 0; i < 4; i++)
#pragma unroll
        for (int j = 0; j < 4; j++) acc[i][j] = 0.f;

    for (int k0 = 0; k0 < 256; k0 += 16) {
        __syncthreads();
#pragma unroll
        for (int it = 0; it < 4; it++) {
            int r = lr + it * 16;
            Xs[lk][r] = X[(row0 + r) * EE + k0 + lk];
            Ws[lk][r] = W[(j0 + r) * EE + k0 + lk];
        }
        __syncthreads();
#pragma unroll
        for (int kk = 0; kk < 16; kk++) {
            float4 xa = *(const float4*)&Xs[kk][ty * 4];
            float4 wb = *(const float4*)&Ws[kk][tx * 4];
            float xr[4] = {xa.x, xa.y, xa.z, xa.w};
            float wr[4] = {wb.x, wb.y, wb.z, wb.w};
#pragma unroll
            for (int i = 0; i < 4; i++)
#pragma unroll
                for (int j = 0; j < 4; j++) acc[i][j] += xr[i] * wr[j];
        }
    }
    // epilogue: add biases (float4), coalesced STG.128 per row
    int jg0 = j0 + tx * 4;
    float4 bi = dir ? *(const float4*)&bihb[jg0] : *(const float4*)&bihf[jg0];
    float4 bh = dir ? *(const float4*)&bhhb[jg0] : *(const float4*)&bhhf[jg0];
    float4 bs = make_float4(bi.x + bh.x, bi.y + bh.y, bi.z + bh.z, bi.w + bh.w);
#pragma unroll
    for (int i = 0; i < 4; i++) {
        int row = row0 + ty * 4 + i;
        int t = row >> 5, b = row & 31;
        float4 v = make_float4(acc[i][0] + bs.x, acc[i][1] + bs.y,
                               acc[i][2] + bs.z, acc[i][3] + bs.w);
        *(float4*)&g_G2[dir][t][b][jg0] = v;
    }
}

// ------------------- persistent recurrent LSTM -------------------
__device__ __forceinline__ float fsig(float x) { return 1.f / (1.f + __expf(-x)); }

__global__ void __launch_bounds__(128, 1)
k_lstm(const float* __restrict__ Whhf, const float* __restrict__ Whhb,
       const float* __restrict__ c0, const int* __restrict__ lens) {
    // static shared: exactly 48KB
    __shared__ __align__(16) float w_sh[256 * 32];   // [v][u_l][gate] 32KB
    __shared__ __align__(16) float h_sh[16 * 256];   // [b_l][v] XOR-swizzled chunks, 16KB

    int bid  = blockIdx.x;
    int dir  = bid >> 6;
    int grp  = (bid >> 5) & 1;
    int grp4 = bid >> 5;               // 0..3 sync group (dir,grp)
    int uslc = bid & 31;
    int tid  = threadIdx.x;            // 128
    int u_l  = tid & 7, b_l = tid >> 3;
    int u = uslc * 8 + u_l;
    int b = grp * 16 + b_l;
    const float* Whh = dir ? Whhb : Whhf;

    // load Whh slice (32 rows): w_sh[v*32 + ul*4 + g] = Whh[(g*256 + uslc*8 + ul)][v]
    for (int i = tid; i < 32 * 256; i += 128) {
        int v = i & 255;
        int ug = i >> 8;                 // ul*4 + g
        int ul2 = ug >> 2, g2 = ug & 3;
        w_sh[v * 32 + ul2 * 4 + g2] = Whh[(g2 * 256 + uslc * 8 + ul2) * HHD + v];
    }
    float c = c0[(dir * BB + b) * HHD + u];
    int len = lens[b];
    int xsw = b_l & 3;
    const float4* w4 = (const float4*)w_sh;
    const unsigned* myctr = &g_ctr[grp4][0];
    __syncthreads();

    for (int t = 0; t < TT; t++) {
        // prefetch gate pre-activations (independent of h)
        const float* gbase = &g_G2[dir][t][b][0];
        float gp0 = __ldg(gbase + u);
        float gp1 = __ldg(gbase + 256 + u);
        float gp2 = __ldg(gbase + 512 + u);
        float gp3 = __ldg(gbase + 768 + u);

        // wait for all 32 peer blocks to have produced step-t input
        if (t > 0 && tid == 0) {
            unsigned v;
            const unsigned* fp = myctr + (t - 1);
            do {
                asm volatile("ld.acquire.gpu.global.u32 %0, [%1];"
                             : "=r"(v) : "l"(fp) : "memory");
            } while (v < 32u);
        }
        __syncthreads();

        // restage h (16 batches x 256) from L2-coherent buffer, XOR-swizzled
        {
            const float4* src = (const float4*)&g_h[t & 1][dir][grp * 16][0];
            for (int i = tid; i < 1024; i += 128) {
                float4 hv = __ldcg(src + i);
                int bb2 = i >> 6, cc = i & 63;
                *(float4*)&h_sh[bb2 * 256 + ((cc ^ (bb2 & 3)) << 2)] = hv;
            }
        }
        __syncthreads();

        // GEMV: 4 gates x 256
        float ai = 0.f, af = 0.f, ag = 0.f, ao = 0.f;
        const float* hrow = h_sh + b_l * 256;
        for (int v = 0; v < 256; v += 4) {
            float4 h4 = *(const float4*)&hrow[((v >> 2) ^ xsw) << 2];
            float4 w0 = w4[(v + 0) * 8 + u_l];
            float4 w1 = w4[(v + 1) * 8 + u_l];
            float4 w2 = w4[(v + 2) * 8 + u_l];
            float4 w3 = w4[(v + 3) * 8 + u_l];
            ai += w0.x * h4.x; af += w0.y * h4.x; ag += w0.z * h4.x; ao += w0.w * h4.x;
            ai += w1.x * h4.y; af += w1.y * h4.y; ag += w1.z * h4.y; ao += w1.w * h4.y;
            ai += w2.x * h4.z; af += w2.y * h4.z; ag += w2.z * h4.z; ao += w2.w * h4.z;
            ai += w3.x * h4.w; af += w3.y * h4.w; ag += w3.z * h4.w; ao += w3.w * h4.w;
        }
        ai += gp0; af += gp1; ag += gp2; ao += gp3;
        float ig = fsig(ai), fg = fsig(af), gg = tanhf(ag), og = fsig(ao);
        c = fg * c + ig * gg;
        float h = og * tanhf(c);

        __stcg(&g_h[(t + 1) & 1][dir][b][u], h);
        int pos = dir ? ((t < len) ? (len - 1 - t) : t) : t;
        g_Hcat[b][pos][dir * 256 + u] = h;

        __syncthreads();   // all CTA stores done (happens-before the release below)
        if (tid == 0) {
            asm volatile("red.release.gpu.global.add.u32 [%0], %1;"
                         :: "l"(myctr + t), "r"(1u) : "memory");
        }
    }
}

// ------------------- emission features: Hcat @ W_out^T + b_out -------------------
__global__ void k_feats(const float* __restrict__ Wout, const float* __restrict__ bout) {
    __shared__ __align__(16) float Wsh[12 * 516];
    __shared__ __align__(16) float Hsh[8 * 516];
    int blk = blockIdx.x;              // 1024 blocks, 8 rows each
    int tid = threadIdx.x;             // 128
    for (int i = tid; i < 12 * 512; i += 128) Wsh[(i >> 9) * 516 + (i & 511)] = Wout[i];
    int row0 = blk * 8;                // row = b*256 + t
    for (int i = tid; i < 8 * 512; i += 128)
        Hsh[(i >> 9) * 516 + (i & 511)] = ((const float*)g_Hcat)[(row0 + (i >> 9)) * 512 + (i & 511)];
    __syncthreads();
    if (tid < 96) {
        int rl = tid / 12, k = tid % 12;
        float s0 = bout[k], s1 = 0.f, s2 = 0.f, s3 = 0.f;
        const float* wr = &Wsh[k * 516];
        const float* hr = &Hsh[rl * 516];
#pragma unroll 8
        for (int hh = 0; hh < 512; hh += 4) {
            float4 a = *(const float4*)&wr[hh];
            float4 bb4 = *(const float4*)&hr[hh];
            s0 += a.x * bb4.x; s1 += a.y * bb4.y; s2 += a.z * bb4.z; s3 += a.w * bb4.w;
        }
        ((float*)g_feats)[(row0 + rl) * 12 + k] = (s0 + s1) + (s2 + s3);
    }
}

// ------------------- Viterbi DP + backtrace -------------------
__global__ void k_viterbi(const float* __restrict__ trans, const int* __restrict__ lens,
                          float* __restrict__ out) {
    __shared__ float tr[144];
    __shared__ float fv[8][13];
    __shared__ unsigned char bp[TT][8][12];
    __shared__ int lsh[8];
    int b0 = blockIdx.x * 8;
    int tid = threadIdx.x;             // 128
    for (int i = tid; i < 144; i += 128) tr[i] = trans[i];
    if (tid < 8) lsh[tid] = lens[b0 + tid];
    int rl = tid / 12, k = tid % 12;
    bool act = tid < 96;
    if (act) fv[rl][k] = (k == TSTART) ? 0.f : NEGV;
    __syncthreads();

    float trk[12];
    if (act) {
#pragma unroll
        for (int p = 0; p < 12; p++) trk[p] = tr[k * 12 + p];
    }
    int len = act ? lsh[rl] : 0;
    int bg = b0 + rl;

    for (int t = 0; t < TT; t++) {
        float nf = 0.f;
        if (act) {
            float feat = ((const float*)g_feats)[(bg * TT + t) * 12 + k];
            float best = fv[rl][0] + trk[0];
            int bpi = 0;
#pragma unroll
            for (int p = 1; p < 12; p++) {
                float s = fv[rl][p] + trk[p];
                if (s > best) { best = s; bpi = p; }   // strict > => first max (jnp.argmax)
            }
            bp[t][rl][k] = (unsigned char)bpi;
            nf = (t < len) ? (best + feat) : fv[rl][k];
        }
        __syncthreads();
        if (act) fv[rl][k] = nf;
        __syncthreads();
    }

    if (tid < 8) {
        int r = tid;
        int bgl = b0 + r;
        int ln = lsh[r];
        float best = fv[r][0] + tr[TSTOP * 12 + 0];
        int tag = 0;
        for (int p = 1; p < 12; p++) {
            float s = fv[r][p] + tr[TSTOP * 12 + p];
            if (s > best) { best = s; tag = p; }
        }
        out[bgl] = best;                               // path score
        for (int t = TT - 1; t >= 0; t--) {
            bool m = t < ln;
            out[BB + bgl * TT + t] = m ? (float)tag : -1.0f;
            if (m) tag = bp[t][r][tag];
        }
    }
}

// ------------------- launch -------------------
extern "C" void kernel_launch(void* const* d_in, const int* in_sizes, int n_in,
                              void* d_out, int out_size) {
    const int*   sent  = (const int*)d_in[0];
    const int*   lens  = (const int*)d_in[1];
    const float* emb   = (const float*)d_in[2];
    const float* Wihf  = (const float*)d_in[3];
    const float* Whhf  = (const float*)d_in[4];
    const float* bihf  = (const float*)d_in[5];
    const float* bhhf  = (const float*)d_in[6];
    const float* Wihb  = (const float*)d_in[7];
    const float* Whhb  = (const float*)d_in[8];
    const float* bihb  = (const float*)d_in[9];
    const float* bhhb  = (const float*)d_in[10];
    const float* h0    = (const float*)d_in[11];
    const float* c0    = (const float*)d_in[12];
    const float* Wout  = (const float*)d_in[13];
    const float* bout  = (const float*)d_in[14];
    const float* trans = (const float*)d_in[15];
    float* out = (float*)d_out;

    k_init<<<64, 256>>>(h0);
    k_gather<<<TT * BB, 256>>>(sent, lens, emb);
    dim3 gg(16, 128, 2);
    k_gemm<<<gg, 256>>>(Wihf, Wihb, bihf, bhhf, bihb, bhhb);
    k_lstm<<<128, 128>>>(Whhf, Whhb, c0, lens);
    k_feats<<<1024, 128>>>(Wout, bout);
    k_viterbi<<<4, 128>>>(trans, lens, out);
}